// round 15
// baseline (speedup 1.0000x reference)
#include <cuda_runtime.h>
#include <cuda_fp16.h>
#include <stdint.h>
#include <math.h>

#define NB 4
#define LT 16384
#define CD 256
#define NH 8
#define DH 32
#define FF 512
#define NLAY 4
#define MTOT (NB*LT)

// ---- fp32 scratch ----
__device__ float g_x[MTOT*CD];
__device__ float g_tmp[MTOT*CD];
__device__ float g_KV[NB*NH*DH*DH];
__device__ float g_Ksum[NB*NH*DH];
// ---- fp16 scratch ----
__device__ __half g_xh[MTOT*CD];
__device__ __half g_qh[MTOT*CD];
__device__ __half g_kh[MTOT*CD];
__device__ __half g_vh[MTOT*CD];
__device__ __half g_ah[MTOT*CD];
__device__ __half g_hh[MTOT*FF];
__device__ __half g_Wqh[NLAY*CD*CD];
__device__ __half g_Wkh[NLAY*CD*CD];
__device__ __half g_Wvh[NLAY*CD*CD];
__device__ __half g_Woh[NLAY*CD*CD];
__device__ __half g_W1h[NLAY*FF*CD];
__device__ __half g_W2h[NLAY*CD*FF];

__device__ __forceinline__ uint32_t smem_u32(const void* p) {
    uint32_t a;
    asm("{ .reg .u64 t; cvta.to.shared.u64 t, %1; cvt.u32.u64 %0, t; }" : "=r"(a) : "l"(p));
    return a;
}
__device__ __forceinline__ void cpa16(uint32_t saddr, const void* g) {
    asm volatile("cp.async.cg.shared.global [%0], [%1], 16;" :: "r"(saddr), "l"(g));
}
#define LDSM4(r0,r1,r2,r3,addr) \
    asm volatile("ldmatrix.sync.aligned.m8n8.x4.shared.b16 {%0,%1,%2,%3}, [%4];" \
        : "=r"(r0),"=r"(r1),"=r"(r2),"=r"(r3) : "r"(addr))
#define MMA16816(c, a, b) \
    asm volatile("mma.sync.aligned.m16n8k16.row.col.f32.f16.f16.f32 " \
        "{%0,%1,%2,%3}, {%4,%5,%6,%7}, {%8,%9}, {%0,%1,%2,%3};" \
        : "+f"((c)[0]),"+f"((c)[1]),"+f"((c)[2]),"+f"((c)[3]) \
        : "r"((a)[0]),"r"((a)[1]),"r"((a)[2]),"r"((a)[3]), "r"((b)[0]),"r"((b)[1]))

__device__ __forceinline__ void st2(float* p, float a, float b) {
    *(float2*)p = make_float2(a, b);
}
__device__ __forceinline__ void st2(__half* p, float a, float b) {
    *(__half2*)p = __floats2half2_rn(a, b);
}

// ============================================================
// HMMA f16 GEMM: C[M,N] = A[M,K] @ B[N,K]^T + bias, ACT 0/1(elu+1)/2(relu)
// 128x128x64 CTA tile, 8 warps (2x4), 3-stage cp.async (96KB dyn smem).
// 128B rows, swizzle chunk^(row&7). K multiple of 64 (S>=2).
// ============================================================
#define STG64 32768
#define GEMM_SMEM (3*STG64)
template<int ACT, typename OutT>
__global__ void __launch_bounds__(256, 2)
gemm_mma(const __half* __restrict__ A, const __half* __restrict__ B,
         const float* __restrict__ bias, OutT* __restrict__ C,
         int M, int N, int K)
{
    extern __shared__ __align__(128) char smem[];
    const int tid = threadIdx.x, wid = tid >> 5, lane = tid & 31;
    const int wm = wid & 1, wn = wid >> 1;
    const int bn = blockIdx.x << 7, bm = blockIdx.y << 7;
    const uint32_t sb = smem_u32(smem);
    const __half* Ag = A + (size_t)bm * K;
    const __half* Bg = B + (size_t)bn * K;
    const int S = K >> 6;

    float acc[4][4][4];
#pragma unroll
    for (int mi = 0; mi < 4; mi++)
#pragma unroll
        for (int ni = 0; ni < 4; ni++)
#pragma unroll
            for (int j = 0; j < 4; j++) acc[mi][ni][j] = 0.f;

    // stage loader: 128 rows x 128B per matrix (A then B), swizzled
    auto load_st = [&](int s) {
        uint32_t dstA = sb + (uint32_t)(s % 3) * STG64;
        uint32_t dstB = dstA + 16384;
        int kt = s << 6;
#pragma unroll
        for (int i = 0; i < 4; i++) {
            int idx = tid + (i << 8);          // 0..1023
            int r = idx >> 3, c = idx & 7;     // row, 16B-chunk
            uint32_t sw = (uint32_t)(c ^ (r & 7));
            cpa16(dstA + r * 128 + (sw << 4), Ag + (size_t)r * K + kt + (c << 3));
            cpa16(dstB + r * 128 + (sw << 4), Bg + (size_t)r * K + kt + (c << 3));
        }
        asm volatile("cp.async.commit_group;" ::: "memory");
    };

    load_st(0);
    load_st(1);

    for (int s = 0; s < S; s++) {
        if (s + 1 < S) asm volatile("cp.async.wait_group 1;" ::: "memory");
        else           asm volatile("cp.async.wait_group 0;" ::: "memory");
        __syncthreads();
        if (s + 2 < S) load_st(s + 2);

        uint32_t bA = sb + (uint32_t)(s % 3) * STG64;
        uint32_t bB = bA + 16384;
#pragma unroll
        for (int ks = 0; ks < 4; ks++) {
            uint32_t af[4][4], bf[4][2];
#pragma unroll
            for (int mi = 0; mi < 4; mi++) {
                int r = wm * 64 + mi * 16 + (lane & 15);
                int c = (ks << 1) + (lane >> 4);
                uint32_t ad = bA + r * 128 + (uint32_t)((c ^ (r & 7)) << 4);
                LDSM4(af[mi][0], af[mi][1], af[mi][2], af[mi][3], ad);
            }
#pragma unroll
            for (int pr = 0; pr < 2; pr++) {
                int n = wn * 32 + pr * 16 + ((lane >> 4) << 3) + (lane & 7);
                int c = (ks << 1) + ((lane >> 3) & 1);
                uint32_t bd = bB + n * 128 + (uint32_t)((c ^ (n & 7)) << 4);
                LDSM4(bf[2*pr][0], bf[2*pr][1], bf[2*pr+1][0], bf[2*pr+1][1], bd);
            }
#pragma unroll
            for (int mi = 0; mi < 4; mi++)
#pragma unroll
                for (int ni = 0; ni < 4; ni++)
                    MMA16816(acc[mi][ni], af[mi], bf[ni]);
        }
        __syncthreads();
    }

    // epilogue
    int g = lane >> 2, tg = lane & 3;
#pragma unroll
    for (int ni = 0; ni < 4; ni++) {
        int col = bn + wn * 32 + ni * 8 + tg * 2;
        float b0 = bias[col], b1 = bias[col + 1];
#pragma unroll
        for (int mi = 0; mi < 4; mi++) {
            int r0 = bm + wm * 64 + mi * 16 + g;
            float v00 = acc[mi][ni][0] + b0, v01 = acc[mi][ni][1] + b1;
            float v10 = acc[mi][ni][2] + b0, v11 = acc[mi][ni][3] + b1;
            if (ACT == 1) {
                v00 = (v00 > 0.f) ? (v00 + 1.f) : expf(v00);
                v01 = (v01 > 0.f) ? (v01 + 1.f) : expf(v01);
                v10 = (v10 > 0.f) ? (v10 + 1.f) : expf(v10);
                v11 = (v11 > 0.f) ? (v11 + 1.f) : expf(v11);
            }
            if (ACT == 2) {
                v00 = fmaxf(v00, 0.f); v01 = fmaxf(v01, 0.f);
                v10 = fmaxf(v10, 0.f); v11 = fmaxf(v11, 0.f);
            }
            st2(C + (size_t)r0 * N + col, v00, v01);
            st2(C + (size_t)(r0 + 8) * N + col, v10, v11);
        }
    }
}

// ============================================================
// single-launch weight conversion (6 arrays)
// ============================================================
__global__ void wconv6(const float* __restrict__ Wq, const float* __restrict__ Wk,
                       const float* __restrict__ Wv, const float* __restrict__ Wo,
                       const float* __restrict__ W1, const float* __restrict__ W2,
                       __half* __restrict__ Wqh, __half* __restrict__ Wkh,
                       __half* __restrict__ Wvh, __half* __restrict__ Woh,
                       __half* __restrict__ W1h, __half* __restrict__ W2h)
{
    const int NC = NLAY*CD*CD/4;   // 65536
    const int NF = NLAY*FF*CD/4;   // 131072
    int i4 = blockIdx.x * blockDim.x + threadIdx.x;
    const float* src; __half* dst; int e;
    if      (i4 < 1*NC)      { e = i4 * 4;            src = Wq; dst = Wqh; }
    else if (i4 < 2*NC)      { e = (i4 - NC) * 4;     src = Wk; dst = Wkh; }
    else if (i4 < 3*NC)      { e = (i4 - 2*NC) * 4;   src = Wv; dst = Wvh; }
    else if (i4 < 4*NC)      { e = (i4 - 3*NC) * 4;   src = Wo; dst = Woh; }
    else if (i4 < 4*NC + NF) { e = (i4 - 4*NC) * 4;   src = W1; dst = W1h; }
    else if (i4 < 4*NC+2*NF) { e = (i4 - 4*NC - NF)*4; src = W2; dst = W2h; }
    else return;
    float4 f = *(const float4*)(src + e);
    __half2 a = __floats2half2_rn(f.x, f.y), b = __floats2half2_rn(f.z, f.w);
    uint2 u; u.x = *(uint32_t*)&a; u.y = *(uint32_t*)&b;
    *(uint2*)(dst + e) = u;
}

// input transpose [CD x LT] -> x [LT x CD] (fp32) + xh (fp16); z = batch
__global__ void transpose_in(const float* __restrict__ in, float* __restrict__ out,
                             __half* __restrict__ outh) {
    __shared__ float tile[32][33];
    int nb = blockIdx.z;
    const float* inb = in + (size_t)nb * CD * LT;
    int bx = blockIdx.x * 32;   // over LT
    int by = blockIdx.y * 32;   // over CD
    int x = bx + threadIdx.x;
#pragma unroll
    for (int j = 0; j < 32; j += 8)
        tile[threadIdx.y + j][threadIdx.x] = inb[(size_t)(by + threadIdx.y + j) * LT + x];
    __syncthreads();
    int x2 = by + threadIdx.x;
    size_t ob = (size_t)nb * LT * CD;
#pragma unroll
    for (int j = 0; j < 32; j += 8) {
        float v = tile[threadIdx.x][threadIdx.y + j];
        size_t o = ob + (size_t)(bx + threadIdx.y + j) * CD + x2;
        out[o] = v;
        outh[o] = __float2half(v);
    }
}

__global__ void zero_kv() {
    int i = blockIdx.x * blockDim.x + threadIdx.x;
    if (i < NB*NH*DH*DH) g_KV[i] = 0.f;
    if (i < NB*NH*DH)    g_Ksum[i] = 0.f;
}

// KV[n,h,m,d] += sum_l K*V over 128-token chunk; fp16 K,V [M, CD]
__global__ void kv_reduce(const __half* __restrict__ Kp, const __half* __restrict__ Vp) {
    __shared__ float sK[128*32];
    __shared__ float sV[128*32];
    int tid = threadIdx.x;
    int l0 = blockIdx.x * 128;
    int nh = blockIdx.y;
    int n = nh >> 3, h = nh & 7;
    const __half* Kb = Kp + (size_t)(n*LT + l0) * CD + h*DH;
    const __half* Vb = Vp + (size_t)(n*LT + l0) * CD + h*DH;
#pragma unroll
    for (int r = 0; r < 2; r++) {
        int f = tid + 256*r;          // 0..511
        int i = f >> 2;               // token 0..127
        int c8 = (f & 3) * 8;         // col group of 8
        uint4 ku = *(const uint4*)(Kb + (size_t)i*CD + c8);
        uint4 vu = *(const uint4*)(Vb + (size_t)i*CD + c8);
        const __half2* kh = (const __half2*)&ku;
        const __half2* vh = (const __half2*)&vu;
#pragma unroll
        for (int j = 0; j < 4; j++) {
            float2 kf = __half22float2(kh[j]);
            float2 vf = __half22float2(vh[j]);
            sK[i*32 + c8 + 2*j]     = kf.x;
            sK[i*32 + c8 + 2*j + 1] = kf.y;
            sV[i*32 + c8 + 2*j]     = vf.x;
            sV[i*32 + c8 + 2*j + 1] = vf.y;
        }
    }
    __syncthreads();
    float acc0=0.f, acc1=0.f, acc2=0.f, acc3=0.f;
    int e0 = tid, e1 = tid+256, e2 = tid+512, e3 = tid+768;
    int m0=e0>>5, d0=e0&31, m1=e1>>5, d1=e1&31, m2=e2>>5, d2=e2&31, m3=e3>>5, d3=e3&31;
#pragma unroll 4
    for (int i = 0; i < 128; i++) {
        const float* kr = &sK[i*32];
        const float* vr = &sV[i*32];
        acc0 += vr[m0]*kr[d0]; acc1 += vr[m1]*kr[d1];
        acc2 += vr[m2]*kr[d2]; acc3 += vr[m3]*kr[d3];
    }
    atomicAdd(&g_KV[nh*1024 + e0], acc0);
    atomicAdd(&g_KV[nh*1024 + e1], acc1);
    atomicAdd(&g_KV[nh*1024 + e2], acc2);
    atomicAdd(&g_KV[nh*1024 + e3], acc3);
    if (tid < 32) {
        float s = 0.f;
#pragma unroll 8
        for (int i = 0; i < 128; i++) s += sK[i*32 + tid];
        atomicAdd(&g_Ksum[nh*32 + tid], s);
    }
}

// attn[n,l,h,m] = Z * sum_d Q[n,l,h,d]*KV[n,h,m,d]; Q fp16 [M,CD], out fp16
__global__ void attn_apply(const __half* __restrict__ Qp, __half* __restrict__ out) {
    __shared__ float sKV[NH*DH*DH];
    __shared__ float sKs[NH*DH];
    int tid = threadIdx.x;
    int n = blockIdx.y;
    int l = blockIdx.x * 32 + (tid >> 3);
    int h = tid & 7;
    const float* kvsrc = g_KV + n*NH*DH*DH;
    for (int i = tid; i < NH*DH*DH; i += 256) sKV[i] = kvsrc[i];
    sKs[tid] = g_Ksum[n*256 + tid];
    __syncthreads();
    float q[32];
    const __half* qp = Qp + (size_t)(n*LT + l) * CD + h*DH;
#pragma unroll
    for (int d8 = 0; d8 < 4; d8++) {
        uint4 qu = *(const uint4*)(qp + d8*8);
        const __half2* qh = (const __half2*)&qu;
#pragma unroll
        for (int j = 0; j < 4; j++) {
            float2 qf = __half22float2(qh[j]);
            q[d8*8 + 2*j]     = qf.x;
            q[d8*8 + 2*j + 1] = qf.y;
        }
    }
    float z = 0.f;
#pragma unroll
    for (int d = 0; d < 32; d++) z += q[d] * sKs[h*32 + d];
    z = 1.f / (z + 1e-6f);
    __half* op = out + (size_t)(n*LT + l) * CD + h*DH;
#pragma unroll 4
    for (int m = 0; m < 32; m++) {
        const float* kvr = &sKV[(h*32 + m) * 32];
        float s = 0.f;
#pragma unroll
        for (int d = 0; d < 32; d++) s += q[d] * kvr[d];
        op[m] = __float2half(s * z);
    }
}

// warp-per-row LN: x = LN(x+y)*g+b (in place) and xh = half(x)
__global__ void ln_residual(float* __restrict__ x, const float* __restrict__ y,
                            const float* __restrict__ g, const float* __restrict__ b,
                            __half* __restrict__ xh) {
    int row = blockIdx.x * 8 + (threadIdx.x >> 5);
    int lane = threadIdx.x & 31;
    size_t base = (size_t)row * CD + lane * 8;
    float4 xa = *(const float4*)(x + base), xb = *(const float4*)(x + base + 4);
    float4 ya = *(const float4*)(y + base), yb = *(const float4*)(y + base + 4);
    float v[8];
    v[0]=xa.x+ya.x; v[1]=xa.y+ya.y; v[2]=xa.z+ya.z; v[3]=xa.w+ya.w;
    v[4]=xb.x+yb.x; v[5]=xb.y+yb.y; v[6]=xb.z+yb.z; v[7]=xb.w+yb.w;
    float s = 0.f;
#pragma unroll
    for (int i = 0; i < 8; i++) s += v[i];
#pragma unroll
    for (int o = 16; o > 0; o >>= 1) s += __shfl_xor_sync(0xffffffffu, s, o);
    float mean = s * (1.f/256.f);
    float var = 0.f;
#pragma unroll
    for (int i = 0; i < 8; i++) { float d = v[i] - mean; var += d*d; }
#pragma unroll
    for (int o = 16; o > 0; o >>= 1) var += __shfl_xor_sync(0xffffffffu, var, o);
    float rs = rsqrtf(var * (1.f/256.f) + 1e-5f);
    float4 ga = *(const float4*)(g + lane*8), gb = *(const float4*)(g + lane*8 + 4);
    float4 ba = *(const float4*)(b + lane*8), bb = *(const float4*)(b + lane*8 + 4);
    float o0[8];
    o0[0]=(v[0]-mean)*rs*ga.x+ba.x; o0[1]=(v[1]-mean)*rs*ga.y+ba.y;
    o0[2]=(v[2]-mean)*rs*ga.z+ba.z; o0[3]=(v[3]-mean)*rs*ga.w+ba.w;
    o0[4]=(v[4]-mean)*rs*gb.x+bb.x; o0[5]=(v[5]-mean)*rs*gb.y+bb.y;
    o0[6]=(v[6]-mean)*rs*gb.z+bb.z; o0[7]=(v[7]-mean)*rs*gb.w+bb.w;
    float4 w0; w0.x=o0[0]; w0.y=o0[1]; w0.z=o0[2]; w0.w=o0[3];
    float4 w1; w1.x=o0[4]; w1.y=o0[5]; w1.z=o0[6]; w1.w=o0[7];
    *(float4*)(x + base) = w0;
    *(float4*)(x + base + 4) = w1;
    __half2 h0=__floats2half2_rn(o0[0],o0[1]), h1=__floats2half2_rn(o0[2],o0[3]);
    __half2 h2=__floats2half2_rn(o0[4],o0[5]), h3=__floats2half2_rn(o0[6],o0[7]);
    uint4 u; u.x=*(uint32_t*)&h0; u.y=*(uint32_t*)&h1; u.z=*(uint32_t*)&h2; u.w=*(uint32_t*)&h3;
    *(uint4*)(xh + base) = u;
}

__global__ void transpose32(const float* __restrict__ in, float* __restrict__ out,
                            int A, int B) {
    __shared__ float tile[32][33];
    int bx = blockIdx.x * 32;
    int by = blockIdx.y * 32;
    int x = bx + threadIdx.x;
#pragma unroll
    for (int j = 0; j < 32; j += 8)
        tile[threadIdx.y + j][threadIdx.x] = in[(size_t)(by + threadIdx.y + j) * B + x];
    __syncthreads();
    int x2 = by + threadIdx.x;
#pragma unroll
    for (int j = 0; j < 32; j += 8)
        out[(size_t)(bx + threadIdx.y + j) * A + x2] = tile[threadIdx.x][threadIdx.y + j];
}

// ============================================================
extern "C" void kernel_launch(void* const* d_in, const int* in_sizes, int n_in,
                              void* d_out, int out_size) {
    const float* ref = (const float*)d_in[0];
    const float* Wq = (const float*)d_in[1];
    const float* bq = (const float*)d_in[2];
    const float* Wk = (const float*)d_in[3];
    const float* bk = (const float*)d_in[4];
    const float* Wv = (const float*)d_in[5];
    const float* bv = (const float*)d_in[6];
    const float* Wo = (const float*)d_in[7];
    const float* bo = (const float*)d_in[8];
    const float* g1 = (const float*)d_in[9];
    const float* be1 = (const float*)d_in[10];
    const float* W1 = (const float*)d_in[11];
    const float* c1 = (const float*)d_in[12];
    const float* W2 = (const float*)d_in[13];
    const float* c2 = (const float*)d_in[14];
    const float* g2 = (const float*)d_in[15];
    const float* be2 = (const float*)d_in[16];
    float* out = (float*)d_out;

    float *px, *ptmp;
    __half *pxh, *pqh, *pkh, *pvh, *pah, *phh, *pWqh, *pWkh, *pWvh, *pWoh, *pW1h, *pW2h;
    cudaGetSymbolAddress((void**)&px, g_x);
    cudaGetSymbolAddress((void**)&ptmp, g_tmp);
    cudaGetSymbolAddress((void**)&pxh, g_xh);
    cudaGetSymbolAddress((void**)&pqh, g_qh);
    cudaGetSymbolAddress((void**)&pkh, g_kh);
    cudaGetSymbolAddress((void**)&pvh, g_vh);
    cudaGetSymbolAddress((void**)&pah, g_ah);
    cudaGetSymbolAddress((void**)&phh, g_hh);
    cudaGetSymbolAddress((void**)&pWqh, g_Wqh);
    cudaGetSymbolAddress((void**)&pWkh, g_Wkh);
    cudaGetSymbolAddress((void**)&pWvh, g_Wvh);
    cudaGetSymbolAddress((void**)&pWoh, g_Woh);
    cudaGetSymbolAddress((void**)&pW1h, g_W1h);
    cudaGetSymbolAddress((void**)&pW2h, g_W2h);

    cudaFuncSetAttribute(gemm_mma<1,__half>, cudaFuncAttributeMaxDynamicSharedMemorySize, GEMM_SMEM);
    cudaFuncSetAttribute(gemm_mma<0,__half>, cudaFuncAttributeMaxDynamicSharedMemorySize, GEMM_SMEM);
    cudaFuncSetAttribute(gemm_mma<0,float>,  cudaFuncAttributeMaxDynamicSharedMemorySize, GEMM_SMEM);
    cudaFuncSetAttribute(gemm_mma<2,__half>, cudaFuncAttributeMaxDynamicSharedMemorySize, GEMM_SMEM);

    // launch 1: weight conversion
    {
        int total = 4*(NLAY*CD*CD/4) + 2*(NLAY*FF*CD/4);
        wconv6<<<(total + 255)/256, 256>>>(Wq, Wk, Wv, Wo, W1, W2,
                                           pWqh, pWkh, pWvh, pWoh, pW1h, pW2h);
    }
    // launch 2: patch embed transpose + fp16
    transpose_in<<<dim3(LT/32, CD/32, NB), dim3(32, 8)>>>(ref, px, pxh);
    // launch 3: zero accumulators for layer 0
    zero_kv<<<(NB*NH*DH*DH + 255)/256, 256>>>();

    dim3 gC(2, MTOT/128);   // N=256
    dim3 gF(4, MTOT/128);   // N=512

    for (int layer = 0; layer < NLAY; layer++) {
        const __half* Wq_l = pWqh + (size_t)layer*CD*CD;  const float* bq_l = bq + layer*CD;
        const __half* Wk_l = pWkh + (size_t)layer*CD*CD;  const float* bk_l = bk + layer*CD;
        const __half* Wv_l = pWvh + (size_t)layer*CD*CD;  const float* bv_l = bv + layer*CD;
        const __half* Wo_l = pWoh + (size_t)layer*CD*CD;  const float* bo_l = bo + layer*CD;
        const __half* W1_l = pW1h + (size_t)layer*FF*CD;  const float* c1_l = c1 + layer*FF;
        const __half* W2_l = pW2h + (size_t)layer*CD*FF;  const float* c2_l = c2 + layer*CD;
        const float* g1_l = g1 + layer*CD;  const float* be1_l = be1 + layer*CD;
        const float* g2_l = g2 + layer*CD;  const float* be2_l = be2 + layer*CD;

        // launches 4,5,6 on first iteration: the QKV GEMMs (ncu lands here)
        gemm_mma<1,__half><<<gC, 256, GEMM_SMEM>>>(pxh, Wq_l, bq_l, pqh, MTOT, CD, CD);
        gemm_mma<1,__half><<<gC, 256, GEMM_SMEM>>>(pxh, Wk_l, bk_l, pkh, MTOT, CD, CD);
        gemm_mma<0,__half><<<gC, 256, GEMM_SMEM>>>(pxh, Wv_l, bv_l, pvh, MTOT, CD, CD);

        kv_reduce<<<dim3(LT/128, NB*NH), 256>>>(pkh, pvh);
        attn_apply<<<dim3(LT/32, NB), 256>>>(pqh, pah);
        if (layer + 1 < NLAY)
            zero_kv<<<(NB*NH*DH*DH + 255)/256, 256>>>();  // for next layer

        gemm_mma<0,float><<<gC, 256, GEMM_SMEM>>>(pah, Wo_l, bo_l, ptmp, MTOT, CD, CD);
        ln_residual<<<MTOT/8, 256>>>(px, ptmp, g1_l, be1_l, pxh);

        gemm_mma<2,__half><<<gF, 256, GEMM_SMEM>>>(pxh, W1_l, c1_l, phh, MTOT, FF, CD);
        gemm_mma<0,float><<<gC, 256, GEMM_SMEM>>>(phh, W2_l, c2_l, ptmp, MTOT, CD, FF);
        ln_residual<<<MTOT/8, 256>>>(px, ptmp, g2_l, be2_l, pxh);

        for (int n = 0; n < NB; n++)
            transpose32<<<dim3(CD/32, LT/32), dim3(32, 8)>>>(
                px + (size_t)n * LT * CD,
                out + ((size_t)layer * NB + n) * CD * LT, LT, CD);
    }
}

// round 16
// speedup vs baseline: 2.0631x; 2.0631x over previous
#include <cuda_runtime.h>
#include <cuda_fp16.h>
#include <stdint.h>
#include <math.h>

#define NB 4
#define LT 16384
#define CD 256
#define NH 8
#define DH 32
#define FF 512
#define NLAY 4
#define MTOT (NB*LT)

// ---- fp32 scratch ----
__device__ float g_x[MTOT*CD];
__device__ float g_tmp[MTOT*CD];
__device__ float g_KV[NB*NH*DH*DH];
__device__ float g_Ksum[NB*NH*DH];
// ---- fp16 scratch ----
__device__ __half g_xh[MTOT*CD];
__device__ __half g_qh[MTOT*CD];
__device__ __half g_kh[MTOT*CD];
__device__ __half g_vh[MTOT*CD];
__device__ __half g_ah[MTOT*CD];
__device__ __half g_hh[MTOT*FF];
__device__ __half g_Wqh[NLAY*CD*CD];
__device__ __half g_Wkh[NLAY*CD*CD];
__device__ __half g_Wvh[NLAY*CD*CD];
__device__ __half g_Woh[NLAY*CD*CD];
__device__ __half g_W1h[NLAY*FF*CD];
__device__ __half g_W2h[NLAY*CD*FF];

__device__ __forceinline__ uint32_t smem_u32(const void* p) {
    uint32_t a;
    asm("{ .reg .u64 t; cvta.to.shared.u64 t, %1; cvt.u32.u64 %0, t; }" : "=r"(a) : "l"(p));
    return a;
}
__device__ __forceinline__ void cpa16(uint32_t saddr, const void* g) {
    asm volatile("cp.async.cg.shared.global [%0], [%1], 16;" :: "r"(saddr), "l"(g));
}
#define LDSM4(r0,r1,r2,r3,addr) \
    asm volatile("ldmatrix.sync.aligned.m8n8.x4.shared.b16 {%0,%1,%2,%3}, [%4];" \
        : "=r"(r0),"=r"(r1),"=r"(r2),"=r"(r3) : "r"(addr))
#define MMA16816(c, a, b) \
    asm volatile("mma.sync.aligned.m16n8k16.row.col.f32.f16.f16.f32 " \
        "{%0,%1,%2,%3}, {%4,%5,%6,%7}, {%8,%9}, {%0,%1,%2,%3};" \
        : "+f"((c)[0]),"+f"((c)[1]),"+f"((c)[2]),"+f"((c)[3]) \
        : "r"((a)[0]),"r"((a)[1]),"r"((a)[2]),"r"((a)[3]), "r"((b)[0]),"r"((b)[1]))

__device__ __forceinline__ void st2(float* p, float a, float b) {
    *(float2*)p = make_float2(a, b);
}
__device__ __forceinline__ void st2(__half* p, float a, float b) {
    *(__half2*)p = __floats2half2_rn(a, b);
}

// ============================================================
// HMMA f16 GEMM: unchanged from R15 (measured 206 TF/s)
// ============================================================
#define STG64 32768
#define GEMM_SMEM (3*STG64)
template<int ACT, typename OutT>
__global__ void __launch_bounds__(256, 2)
gemm_mma(const __half* __restrict__ A, const __half* __restrict__ B,
         const float* __restrict__ bias, OutT* __restrict__ C,
         int M, int N, int K)
{
    extern __shared__ __align__(128) char smem[];
    const int tid = threadIdx.x, wid = tid >> 5, lane = tid & 31;
    const int wm = wid & 1, wn = wid >> 1;
    const int bn = blockIdx.x << 7, bm = blockIdx.y << 7;
    const uint32_t sb = smem_u32(smem);
    const __half* Ag = A + (size_t)bm * K;
    const __half* Bg = B + (size_t)bn * K;
    const int S = K >> 6;

    float acc[4][4][4];
#pragma unroll
    for (int mi = 0; mi < 4; mi++)
#pragma unroll
        for (int ni = 0; ni < 4; ni++)
#pragma unroll
            for (int j = 0; j < 4; j++) acc[mi][ni][j] = 0.f;

    auto load_st = [&](int s) {
        uint32_t dstA = sb + (uint32_t)(s % 3) * STG64;
        uint32_t dstB = dstA + 16384;
        int kt = s << 6;
#pragma unroll
        for (int i = 0; i < 4; i++) {
            int idx = tid + (i << 8);
            int r = idx >> 3, c = idx & 7;
            uint32_t sw = (uint32_t)(c ^ (r & 7));
            cpa16(dstA + r * 128 + (sw << 4), Ag + (size_t)r * K + kt + (c << 3));
            cpa16(dstB + r * 128 + (sw << 4), Bg + (size_t)r * K + kt + (c << 3));
        }
        asm volatile("cp.async.commit_group;" ::: "memory");
    };

    load_st(0);
    load_st(1);

    for (int s = 0; s < S; s++) {
        if (s + 1 < S) asm volatile("cp.async.wait_group 1;" ::: "memory");
        else           asm volatile("cp.async.wait_group 0;" ::: "memory");
        __syncthreads();
        if (s + 2 < S) load_st(s + 2);

        uint32_t bA = sb + (uint32_t)(s % 3) * STG64;
        uint32_t bB = bA + 16384;
#pragma unroll
        for (int ks = 0; ks < 4; ks++) {
            uint32_t af[4][4], bf[4][2];
#pragma unroll
            for (int mi = 0; mi < 4; mi++) {
                int r = wm * 64 + mi * 16 + (lane & 15);
                int c = (ks << 1) + (lane >> 4);
                uint32_t ad = bA + r * 128 + (uint32_t)((c ^ (r & 7)) << 4);
                LDSM4(af[mi][0], af[mi][1], af[mi][2], af[mi][3], ad);
            }
#pragma unroll
            for (int pr = 0; pr < 2; pr++) {
                int n = wn * 32 + pr * 16 + ((lane >> 4) << 3) + (lane & 7);
                int c = (ks << 1) + ((lane >> 3) & 1);
                uint32_t bd = bB + n * 128 + (uint32_t)((c ^ (n & 7)) << 4);
                LDSM4(bf[2*pr][0], bf[2*pr][1], bf[2*pr+1][0], bf[2*pr+1][1], bd);
            }
#pragma unroll
            for (int mi = 0; mi < 4; mi++)
#pragma unroll
                for (int ni = 0; ni < 4; ni++)
                    MMA16816(acc[mi][ni], af[mi], bf[ni]);
        }
        __syncthreads();
    }

    int g = lane >> 2, tg = lane & 3;
#pragma unroll
    for (int ni = 0; ni < 4; ni++) {
        int col = bn + wn * 32 + ni * 8 + tg * 2;
        float b0 = bias[col], b1 = bias[col + 1];
#pragma unroll
        for (int mi = 0; mi < 4; mi++) {
            int r0 = bm + wm * 64 + mi * 16 + g;
            float v00 = acc[mi][ni][0] + b0, v01 = acc[mi][ni][1] + b1;
            float v10 = acc[mi][ni][2] + b0, v11 = acc[mi][ni][3] + b1;
            if (ACT == 1) {
                v00 = (v00 > 0.f) ? (v00 + 1.f) : expf(v00);
                v01 = (v01 > 0.f) ? (v01 + 1.f) : expf(v01);
                v10 = (v10 > 0.f) ? (v10 + 1.f) : expf(v10);
                v11 = (v11 > 0.f) ? (v11 + 1.f) : expf(v11);
            }
            if (ACT == 2) {
                v00 = fmaxf(v00, 0.f); v01 = fmaxf(v01, 0.f);
                v10 = fmaxf(v10, 0.f); v11 = fmaxf(v11, 0.f);
            }
            st2(C + (size_t)r0 * N + col, v00, v01);
            st2(C + (size_t)(r0 + 8) * N + col, v10, v11);
        }
    }
}

// ============================================================
__global__ void wconv6(const float* __restrict__ Wq, const float* __restrict__ Wk,
                       const float* __restrict__ Wv, const float* __restrict__ Wo,
                       const float* __restrict__ W1, const float* __restrict__ W2,
                       __half* __restrict__ Wqh, __half* __restrict__ Wkh,
                       __half* __restrict__ Wvh, __half* __restrict__ Woh,
                       __half* __restrict__ W1h, __half* __restrict__ W2h)
{
    const int NC = NLAY*CD*CD/4;
    const int NF = NLAY*FF*CD/4;
    int i4 = blockIdx.x * blockDim.x + threadIdx.x;
    const float* src; __half* dst; int e;
    if      (i4 < 1*NC)      { e = i4 * 4;            src = Wq; dst = Wqh; }
    else if (i4 < 2*NC)      { e = (i4 - NC) * 4;     src = Wk; dst = Wkh; }
    else if (i4 < 3*NC)      { e = (i4 - 2*NC) * 4;   src = Wv; dst = Wvh; }
    else if (i4 < 4*NC)      { e = (i4 - 3*NC) * 4;   src = Wo; dst = Woh; }
    else if (i4 < 4*NC + NF) { e = (i4 - 4*NC) * 4;   src = W1; dst = W1h; }
    else if (i4 < 4*NC+2*NF) { e = (i4 - 4*NC - NF)*4; src = W2; dst = W2h; }
    else return;
    float4 f = *(const float4*)(src + e);
    __half2 a = __floats2half2_rn(f.x, f.y), b = __floats2half2_rn(f.z, f.w);
    uint2 u; u.x = *(uint32_t*)&a; u.y = *(uint32_t*)&b;
    *(uint2*)(dst + e) = u;
}

__global__ void transpose_in(const float* __restrict__ in, float* __restrict__ out,
                             __half* __restrict__ outh) {
    __shared__ float tile[32][33];
    int nb = blockIdx.z;
    const float* inb = in + (size_t)nb * CD * LT;
    int bx = blockIdx.x * 32;
    int by = blockIdx.y * 32;
    int x = bx + threadIdx.x;
#pragma unroll
    for (int j = 0; j < 32; j += 8)
        tile[threadIdx.y + j][threadIdx.x] = inb[(size_t)(by + threadIdx.y + j) * LT + x];
    __syncthreads();
    int x2 = by + threadIdx.x;
    size_t ob = (size_t)nb * LT * CD;
#pragma unroll
    for (int j = 0; j < 32; j += 8) {
        float v = tile[threadIdx.x][threadIdx.y + j];
        size_t o = ob + (size_t)(bx + threadIdx.y + j) * CD + x2;
        out[o] = v;
        outh[o] = __float2half(v);
    }
}

__global__ void zero_kv() {
    int i = blockIdx.x * blockDim.x + threadIdx.x;
    if (i < NB*NH*DH*DH) g_KV[i] = 0.f;
    if (i < NB*NH*DH)    g_Ksum[i] = 0.f;
}

// ============================================================
// kv_reduce v2: register-blocked 4x4 (m,d) tiles, conflict-free smem.
// grid (LT/512, NB*NH), block 256 = 4 groups of 64 threads.
// Each group: 8x8 map t=(m4*8+d4); processes 32 tokens per 128-token stage.
// ============================================================
__global__ void kv_reduce(const __half* __restrict__ Kp, const __half* __restrict__ Vp) {
    __shared__ __align__(16) float sK[128*36];
    __shared__ __align__(16) float sV[128*36];
    const int tid = threadIdx.x;
    const int nh = blockIdx.y;
    const int n = nh >> 3, h = nh & 7;
    const int ggrp = tid >> 6;          // group 0..3
    const int t = tid & 63;
    const int m4 = t >> 3, d4 = t & 7;  // 8x8 tiles of 4x4
    const __half* Kb = Kp + (size_t)(n*LT + blockIdx.x*512) * CD + h*DH;
    const __half* Vb = Vp + (size_t)(n*LT + blockIdx.x*512) * CD + h*DH;

    float acc[16];
#pragma unroll
    for (int i = 0; i < 16; i++) acc[i] = 0.f;
    float ks[4] = {0.f, 0.f, 0.f, 0.f};

    for (int ss = 0; ss < 4; ss++) {
        // load 128 tokens x 32 (K and V) fp16 -> fp32 smem (rows padded to 36)
        __syncthreads();
#pragma unroll
        for (int jj = 0; jj < 4; jj++) {
            int j = tid + (jj << 8);           // 0..1023
            int mat = j >> 9;                  // 0=K,1=V
            int idx = j & 511;
            int tok = idx >> 2, c = idx & 3;   // 4 chunks of 8 halfs
            const __half* src = (mat ? Vb : Kb) + (size_t)(ss*128 + tok) * CD + c*8;
            uint4 u = *(const uint4*)src;
            const __half2* hh2 = (const __half2*)&u;
            float* dst = (mat ? sV : sK) + tok*36 + c*8;
            float2 f0 = __half22float2(hh2[0]);
            float2 f1 = __half22float2(hh2[1]);
            float2 f2 = __half22float2(hh2[2]);
            float2 f3 = __half22float2(hh2[3]);
            float4 w0; w0.x=f0.x; w0.y=f0.y; w0.z=f1.x; w0.w=f1.y;
            float4 w1; w1.x=f2.x; w1.y=f2.y; w1.z=f3.x; w1.w=f3.y;
            *(float4*)dst = w0;
            *(float4*)(dst + 4) = w1;
        }
        __syncthreads();
        // compute: group g handles tokens [g*32, g*32+32)
        const float* kbase = sK + (ggrp*32)*36 + d4*4;
        const float* vbase = sV + (ggrp*32)*36 + m4*4;
#pragma unroll 4
        for (int i = 0; i < 32; i++) {
            float4 kk = *(const float4*)(kbase + i*36);
            float4 vv = *(const float4*)(vbase + i*36);
            acc[0]  += vv.x*kk.x; acc[1]  += vv.x*kk.y; acc[2]  += vv.x*kk.z; acc[3]  += vv.x*kk.w;
            acc[4]  += vv.y*kk.x; acc[5]  += vv.y*kk.y; acc[6]  += vv.y*kk.z; acc[7]  += vv.y*kk.w;
            acc[8]  += vv.z*kk.x; acc[9]  += vv.z*kk.y; acc[10] += vv.z*kk.z; acc[11] += vv.z*kk.w;
            acc[12] += vv.w*kk.x; acc[13] += vv.w*kk.y; acc[14] += vv.w*kk.z; acc[15] += vv.w*kk.w;
            if (m4 == 0) { ks[0] += kk.x; ks[1] += kk.y; ks[2] += kk.z; ks[3] += kk.w; }
        }
    }
    // cross-group reduction in smem (alias sK/sV), then atomics
    __syncthreads();
    float* sRed = sK;                 // 256*16 = 4096 floats (fits 4608)
    float* sKs  = sV;                 // 4*32 = 128 floats
#pragma unroll
    for (int i = 0; i < 16; i++) sRed[tid*16 + i] = acc[i];
    if (m4 == 0) {
#pragma unroll
        for (int i = 0; i < 4; i++) sKs[ggrp*32 + d4*4 + i] = ks[i];
    }
    __syncthreads();
    if (tid < 64) {
        int mm4 = tid >> 3, dd4 = tid & 7;
#pragma unroll
        for (int i = 0; i < 16; i++) {
            float s = sRed[tid*16 + i] + sRed[(64+tid)*16 + i]
                    + sRed[(128+tid)*16 + i] + sRed[(192+tid)*16 + i];
            int mi = i >> 2, di = i & 3;
            atomicAdd(&g_KV[nh*1024 + (mm4*4+mi)*32 + dd4*4+di], s);
        }
    } else if (tid < 96) {
        int d = tid - 64;
        float s = sKs[d] + sKs[32+d] + sKs[64+d] + sKs[96+d];
        atomicAdd(&g_Ksum[nh*32 + d], s);
    }
}

// ============================================================
// attn_apply v2: conflict-free padded KV (head stride 1028), q in regs.
// grid (LT/32, NB), block 256; thread = (token tid>>3, head tid&7).
// ============================================================
__global__ void attn_apply(const __half* __restrict__ Qp, __half* __restrict__ out) {
    __shared__ __align__(16) float sKVp[NH*1028];
    __shared__ float sKsp[NH*33];
    const int tid = threadIdx.x;
    const int n = blockIdx.y;
    const int l = blockIdx.x * 32 + (tid >> 3);
    const int h = tid & 7;
    const float* kvsrc = g_KV + n*NH*DH*DH;
    for (int i = tid; i < NH*DH*DH; i += 256)
        sKVp[(i >> 10)*1028 + (i & 1023)] = kvsrc[i];
    {
        int hh = tid >> 5, d = tid & 31;
        sKsp[hh*33 + d] = g_Ksum[n*256 + hh*32 + d];
    }
    __syncthreads();

    float q[32];
    const __half* qp = Qp + (size_t)(n*LT + l) * CD + h*DH;
#pragma unroll
    for (int d8 = 0; d8 < 4; d8++) {
        uint4 qu = *(const uint4*)(qp + d8*8);
        const __half2* qh = (const __half2*)&qu;
#pragma unroll
        for (int j = 0; j < 4; j++) {
            float2 qf = __half22float2(qh[j]);
            q[d8*8 + 2*j]     = qf.x;
            q[d8*8 + 2*j + 1] = qf.y;
        }
    }
    float z = 0.f;
#pragma unroll
    for (int d = 0; d < 32; d++) z += q[d] * sKsp[h*33 + d];
    z = 1.f / (z + 1e-6f);

    const float* kvh = sKVp + h*1028;
    __half* op = out + (size_t)(n*LT + l) * CD + h*DH;
#pragma unroll 2
    for (int mp = 0; mp < 8; mp++) {
        float o4[4];
#pragma unroll
        for (int mi = 0; mi < 4; mi++) {
            int m = mp*4 + mi;
            const float* kvr = kvh + m*32;
            float s0 = 0.f, s1 = 0.f;
#pragma unroll
            for (int c = 0; c < 8; c += 2) {
                float4 a = *(const float4*)(kvr + c*4);
                float4 b = *(const float4*)(kvr + c*4 + 4);
                s0 += q[c*4+0]*a.x + q[c*4+1]*a.y + q[c*4+2]*a.z + q[c*4+3]*a.w;
                s1 += q[c*4+4]*b.x + q[c*4+5]*b.y + q[c*4+6]*b.z + q[c*4+7]*b.w;
            }
            o4[mi] = (s0 + s1) * z;
        }
        __half2 h0 = __floats2half2_rn(o4[0], o4[1]);
        __half2 h1 = __floats2half2_rn(o4[2], o4[3]);
        uint2 u; u.x = *(uint32_t*)&h0; u.y = *(uint32_t*)&h1;
        *(uint2*)(op + mp*4) = u;
    }
}

// warp-per-row LN: x = LN(x+y)*g+b (in place) and xh = half(x)
__global__ void ln_residual(float* __restrict__ x, const float* __restrict__ y,
                            const float* __restrict__ g, const float* __restrict__ b,
                            __half* __restrict__ xh) {
    int row = blockIdx.x * 8 + (threadIdx.x >> 5);
    int lane = threadIdx.x & 31;
    size_t base = (size_t)row * CD + lane * 8;
    float4 xa = *(const float4*)(x + base), xb = *(const float4*)(x + base + 4);
    float4 ya = *(const float4*)(y + base), yb = *(const float4*)(y + base + 4);
    float v[8];
    v[0]=xa.x+ya.x; v[1]=xa.y+ya.y; v[2]=xa.z+ya.z; v[3]=xa.w+ya.w;
    v[4]=xb.x+yb.x; v[5]=xb.y+yb.y; v[6]=xb.z+yb.z; v[7]=xb.w+yb.w;
    float s = 0.f;
#pragma unroll
    for (int i = 0; i < 8; i++) s += v[i];
#pragma unroll
    for (int o = 16; o > 0; o >>= 1) s += __shfl_xor_sync(0xffffffffu, s, o);
    float mean = s * (1.f/256.f);
    float var = 0.f;
#pragma unroll
    for (int i = 0; i < 8; i++) { float d = v[i] - mean; var += d*d; }
#pragma unroll
    for (int o = 16; o > 0; o >>= 1) var += __shfl_xor_sync(0xffffffffu, var, o);
    float rs = rsqrtf(var * (1.f/256.f) + 1e-5f);
    float4 ga = *(const float4*)(g + lane*8), gb = *(const float4*)(g + lane*8 + 4);
    float4 ba = *(const float4*)(b + lane*8), bb = *(const float4*)(b + lane*8 + 4);
    float o0[8];
    o0[0]=(v[0]-mean)*rs*ga.x+ba.x; o0[1]=(v[1]-mean)*rs*ga.y+ba.y;
    o0[2]=(v[2]-mean)*rs*ga.z+ba.z; o0[3]=(v[3]-mean)*rs*ga.w+ba.w;
    o0[4]=(v[4]-mean)*rs*gb.x+bb.x; o0[5]=(v[5]-mean)*rs*gb.y+bb.y;
    o0[6]=(v[6]-mean)*rs*gb.z+bb.z; o0[7]=(v[7]-mean)*rs*gb.w+bb.w;
    float4 w0; w0.x=o0[0]; w0.y=o0[1]; w0.z=o0[2]; w0.w=o0[3];
    float4 w1; w1.x=o0[4]; w1.y=o0[5]; w1.z=o0[6]; w1.w=o0[7];
    *(float4*)(x + base) = w0;
    *(float4*)(x + base + 4) = w1;
    __half2 h0=__floats2half2_rn(o0[0],o0[1]), h1=__floats2half2_rn(o0[2],o0[3]);
    __half2 h2=__floats2half2_rn(o0[4],o0[5]), h3=__floats2half2_rn(o0[6],o0[7]);
    uint4 u; u.x=*(uint32_t*)&h0; u.y=*(uint32_t*)&h1; u.z=*(uint32_t*)&h2; u.w=*(uint32_t*)&h3;
    *(uint4*)(xh + base) = u;
}

__global__ void transpose32(const float* __restrict__ in, float* __restrict__ out,
                            int A, int B) {
    __shared__ float tile[32][33];
    int bx = blockIdx.x * 32;
    int by = blockIdx.y * 32;
    int x = bx + threadIdx.x;
#pragma unroll
    for (int j = 0; j < 32; j += 8)
        tile[threadIdx.y + j][threadIdx.x] = in[(size_t)(by + threadIdx.y + j) * B + x];
    __syncthreads();
    int x2 = by + threadIdx.x;
#pragma unroll
    for (int j = 0; j < 32; j += 8)
        out[(size_t)(bx + threadIdx.y + j) * A + x2] = tile[threadIdx.x][threadIdx.y + j];
}

// ============================================================
extern "C" void kernel_launch(void* const* d_in, const int* in_sizes, int n_in,
                              void* d_out, int out_size) {
    const float* ref = (const float*)d_in[0];
    const float* Wq = (const float*)d_in[1];
    const float* bq = (const float*)d_in[2];
    const float* Wk = (const float*)d_in[3];
    const float* bk = (const float*)d_in[4];
    const float* Wv = (const float*)d_in[5];
    const float* bv = (const float*)d_in[6];
    const float* Wo = (const float*)d_in[7];
    const float* bo = (const float*)d_in[8];
    const float* g1 = (const float*)d_in[9];
    const float* be1 = (const float*)d_in[10];
    const float* W1 = (const float*)d_in[11];
    const float* c1 = (const float*)d_in[12];
    const float* W2 = (const float*)d_in[13];
    const float* c2 = (const float*)d_in[14];
    const float* g2 = (const float*)d_in[15];
    const float* be2 = (const float*)d_in[16];
    float* out = (float*)d_out;

    float *px, *ptmp;
    __half *pxh, *pqh, *pkh, *pvh, *pah, *phh, *pWqh, *pWkh, *pWvh, *pWoh, *pW1h, *pW2h;
    cudaGetSymbolAddress((void**)&px, g_x);
    cudaGetSymbolAddress((void**)&ptmp, g_tmp);
    cudaGetSymbolAddress((void**)&pxh, g_xh);
    cudaGetSymbolAddress((void**)&pqh, g_qh);
    cudaGetSymbolAddress((void**)&pkh, g_kh);
    cudaGetSymbolAddress((void**)&pvh, g_vh);
    cudaGetSymbolAddress((void**)&pah, g_ah);
    cudaGetSymbolAddress((void**)&phh, g_hh);
    cudaGetSymbolAddress((void**)&pWqh, g_Wqh);
    cudaGetSymbolAddress((void**)&pWkh, g_Wkh);
    cudaGetSymbolAddress((void**)&pWvh, g_Wvh);
    cudaGetSymbolAddress((void**)&pWoh, g_Woh);
    cudaGetSymbolAddress((void**)&pW1h, g_W1h);
    cudaGetSymbolAddress((void**)&pW2h, g_W2h);

    cudaFuncSetAttribute(gemm_mma<1,__half>, cudaFuncAttributeMaxDynamicSharedMemorySize, GEMM_SMEM);
    cudaFuncSetAttribute(gemm_mma<0,__half>, cudaFuncAttributeMaxDynamicSharedMemorySize, GEMM_SMEM);
    cudaFuncSetAttribute(gemm_mma<0,float>,  cudaFuncAttributeMaxDynamicSharedMemorySize, GEMM_SMEM);
    cudaFuncSetAttribute(gemm_mma<2,__half>, cudaFuncAttributeMaxDynamicSharedMemorySize, GEMM_SMEM);

    {
        int total = 4*(NLAY*CD*CD/4) + 2*(NLAY*FF*CD/4);
        wconv6<<<(total + 255)/256, 256>>>(Wq, Wk, Wv, Wo, W1, W2,
                                           pWqh, pWkh, pWvh, pWoh, pW1h, pW2h);
    }
    transpose_in<<<dim3(LT/32, CD/32, NB), dim3(32, 8)>>>(ref, px, pxh);
    zero_kv<<<(NB*NH*DH*DH + 255)/256, 256>>>();

    dim3 gC(2, MTOT/128);   // N=256
    dim3 gF(4, MTOT/128);   // N=512

    for (int layer = 0; layer < NLAY; layer++) {
        const __half* Wq_l = pWqh + (size_t)layer*CD*CD;  const float* bq_l = bq + layer*CD;
        const __half* Wk_l = pWkh + (size_t)layer*CD*CD;  const float* bk_l = bk + layer*CD;
        const __half* Wv_l = pWvh + (size_t)layer*CD*CD;  const float* bv_l = bv + layer*CD;
        const __half* Wo_l = pWoh + (size_t)layer*CD*CD;  const float* bo_l = bo + layer*CD;
        const __half* W1_l = pW1h + (size_t)layer*FF*CD;  const float* c1_l = c1 + layer*FF;
        const __half* W2_l = pW2h + (size_t)layer*CD*FF;  const float* c2_l = c2 + layer*CD;
        const float* g1_l = g1 + layer*CD;  const float* be1_l = be1 + layer*CD;
        const float* g2_l = g2 + layer*CD;  const float* be2_l = be2 + layer*CD;

        gemm_mma<1,__half><<<gC, 256, GEMM_SMEM>>>(pxh, Wq_l, bq_l, pqh, MTOT, CD, CD);
        gemm_mma<1,__half><<<gC, 256, GEMM_SMEM>>>(pxh, Wk_l, bk_l, pkh, MTOT, CD, CD);
        gemm_mma<0,__half><<<gC, 256, GEMM_SMEM>>>(pxh, Wv_l, bv_l, pvh, MTOT, CD, CD);

        kv_reduce<<<dim3(LT/512, NB*NH), 256>>>(pkh, pvh);
        attn_apply<<<dim3(LT/32, NB), 256>>>(pqh, pah);
        if (layer + 1 < NLAY)
            zero_kv<<<(NB*NH*DH*DH + 255)/256, 256>>>();

        gemm_mma<0,float><<<gC, 256, GEMM_SMEM>>>(pah, Wo_l, bo_l, ptmp, MTOT, CD, CD);
        ln_residual<<<MTOT/8, 256>>>(px, ptmp, g1_l, be1_l, pxh);

        gemm_mma<2,__half><<<gF, 256, GEMM_SMEM>>>(pxh, W1_l, c1_l, phh, MTOT, FF, CD);
        gemm_mma<0,float><<<gC, 256, GEMM_SMEM>>>(phh, W2_l, c2_l, ptmp, MTOT, CD, FF);
        ln_residual<<<MTOT/8, 256>>>(px, ptmp, g2_l, be2_l, pxh);

        for (int n = 0; n < NB; n++)
            transpose32<<<dim3(CD/32, LT/32), dim3(32, 8)>>>(
                px + (size_t)n * LT * CD,
                out + ((size_t)layer * NB + n) * CD * LT, LT, CD);
    }
}